// round 1
// baseline (speedup 1.0000x reference)
#include <cuda_runtime.h>

#define N_NODES  200000
#define N_CHILD  32
#define N_LAYERS 8

// Ping-pong value buffers (no runtime allocation allowed).
__device__ float g_bufA[N_NODES];
__device__ float g_bufB[N_NODES];

// One warp processes 4 nodes:
//   lane k loads int4 of child indices covering flat [warp_nodes*32 + 4k, +4)
//   -> lanes 0-7 hold node0's 32 children, 8-15 node1, 16-23 node2, 24-31 node3.
// Each lane gathers 4 values (independent loads -> MLP), partial-sums, then a
// 3-step shfl reduction within each 8-lane group produces the node sum.
__global__ void __launch_bounds__(256) layer_kernel(
    const float* __restrict__ vals,
    float*       __restrict__ out,
    const int4*  __restrict__ cidx,   // this layer's [N_NODES*N_CHILD] as int4
    const int*   __restrict__ fids,   // this layer's [N_NODES]
    const float* __restrict__ wptr)
{
    const int warp = (blockIdx.x * blockDim.x + threadIdx.x) >> 5;
    const int lane = threadIdx.x & 31;
    const int node_base = warp * 4;
    if (node_base >= N_NODES) return;

    // Coalesced index load: warp reads 512B contiguous.
    const int4 c = cidx[(size_t)node_base * (N_CHILD / 4) + lane];

    float s = __ldg(vals + c.x) + __ldg(vals + c.y)
            + __ldg(vals + c.z) + __ldg(vals + c.w);

    // Reduce within 8-lane groups (offsets stay inside the group).
    s += __shfl_down_sync(0xffffffffu, s, 4);
    s += __shfl_down_sync(0xffffffffu, s, 2);
    s += __shfl_down_sync(0xffffffffu, s, 1);

    if ((lane & 7) == 0) {
        const int node = node_base + (lane >> 3);
        const float x = wptr[0] * s;
        const int fid = __ldg(fids + node);
        float r;
        if      (fid == 0) r = tanhf(x);
        else if (fid == 1) r = 1.0f / (1.0f + expf(-x));
        else if (fid == 2) r = fmaxf(x, 0.0f);
        else               r = x;
        out[node] = r;
    }
}

extern "C" void kernel_launch(void* const* d_in, const int* in_sizes, int n_in,
                              void* d_out, int out_size)
{
    const float* X    = (const float*)d_in[0];
    const float* w    = (const float*)d_in[1];
    const int*   cidx = (const int*)  d_in[2];  // [N_LAYERS, N_NODES, N_CHILD]
    const int*   fids = (const int*)  d_in[3];  // [N_LAYERS, N_NODES]
    float*       out  = (float*)d_out;

    float* bufA = nullptr;
    float* bufB = nullptr;
    cudaGetSymbolAddress((void**)&bufA, g_bufA);
    cudaGetSymbolAddress((void**)&bufB, g_bufB);

    // Layer i reads ins[i], writes outs[i].
    const float* ins[N_LAYERS]  = { X, bufA, bufB, bufA, bufB, bufA, bufB, bufA };
    float*       outs[N_LAYERS] = { bufA, bufB, bufA, bufB, bufA, bufB, bufA, out };

    // 200000 nodes / 4 nodes-per-warp = 50000 warps; 256 threads = 8 warps/block.
    const int threads = 256;
    const int blocks  = (N_NODES / 4 * 32 + threads - 1) / threads;  // 6250

    for (int l = 0; l < N_LAYERS; l++) {
        const int4* layer_cidx =
            (const int4*)(cidx + (size_t)l * N_NODES * N_CHILD);
        const int* layer_fids = fids + (size_t)l * N_NODES;
        layer_kernel<<<blocks, threads>>>(ins[l], outs[l], layer_cidx,
                                          layer_fids, w);
    }
}

// round 2
// speedup vs baseline: 1.0756x; 1.0756x over previous
#include <cuda_runtime.h>

#define N_NODES  200000
#define N_CHILD  32
#define N_LAYERS 8

// Ping-pong value buffers (no runtime allocation allowed).
__device__ float g_bufA[N_NODES];
__device__ float g_bufB[N_NODES];

// One warp processes 8 nodes (two groups of 4):
//   lane k loads int4 #k  (group A: nodes 0..3 of the 8)  and
//                int4 #k+32 (group B: nodes 4..7 of the 8)
//   -> int4 j covers node j/8's children [(j%8)*4, +4).
// Both index loads are issued back-to-back (2 outstanding DRAM loads/lane),
// then all 8 gathers/lane are in flight (MLP=8) before any summation.
// Index/fids streams use .cs (evict-first) so the 800KB vals array keeps
// L1 residency for the gathers.
__global__ void __launch_bounds__(256) layer_kernel(
    const float* __restrict__ vals,
    float*       __restrict__ out,
    const int4*  __restrict__ cidx,   // this layer's [N_NODES*N_CHILD] as int4
    const int*   __restrict__ fids,   // this layer's [N_NODES]
    const float* __restrict__ wptr)
{
    const int warp = (blockIdx.x * blockDim.x + threadIdx.x) >> 5;
    const int lane = threadIdx.x & 31;
    const int node_base = warp * 8;
    if (node_base >= N_NODES) return;

    // Coalesced, streaming (evict-first) index loads: 1KB contiguous per warp.
    const size_t ibase = (size_t)node_base * (N_CHILD / 4);
    const int4 cA = __ldcs(cidx + ibase + lane);
    const int4 cB = __ldcs(cidx + ibase + 32 + lane);

    // 8 independent gathers per lane — let ptxas front-batch them.
    const float a0 = __ldg(vals + cA.x);
    const float a1 = __ldg(vals + cA.y);
    const float a2 = __ldg(vals + cA.z);
    const float a3 = __ldg(vals + cA.w);
    const float b0 = __ldg(vals + cB.x);
    const float b1 = __ldg(vals + cB.y);
    const float b2 = __ldg(vals + cB.z);
    const float b3 = __ldg(vals + cB.w);

    float sA = (a0 + a1) + (a2 + a3);
    float sB = (b0 + b1) + (b2 + b3);

    // Reduce within 8-lane groups (offsets stay inside the group).
    sA += __shfl_down_sync(0xffffffffu, sA, 4);
    sB += __shfl_down_sync(0xffffffffu, sB, 4);
    sA += __shfl_down_sync(0xffffffffu, sA, 2);
    sB += __shfl_down_sync(0xffffffffu, sB, 2);
    sA += __shfl_down_sync(0xffffffffu, sA, 1);
    sB += __shfl_down_sync(0xffffffffu, sB, 1);

    if ((lane & 7) == 0) {
        const int g = lane >> 3;
        const float wv = wptr[0];

        const int nodeA = node_base + g;
        const int fidA  = __ldcs(fids + nodeA);
        const float xA  = wv * sA;
        float rA;
        if      (fidA == 0) rA = tanhf(xA);
        else if (fidA == 1) rA = 1.0f / (1.0f + expf(-xA));
        else if (fidA == 2) rA = fmaxf(xA, 0.0f);
        else                rA = xA;
        out[nodeA] = rA;

        const int nodeB = node_base + 4 + g;
        const int fidB  = __ldcs(fids + nodeB);
        const float xB  = wv * sB;
        float rB;
        if      (fidB == 0) rB = tanhf(xB);
        else if (fidB == 1) rB = 1.0f / (1.0f + expf(-xB));
        else if (fidB == 2) rB = fmaxf(xB, 0.0f);
        else                rB = xB;
        out[nodeB] = rB;
    }
}

extern "C" void kernel_launch(void* const* d_in, const int* in_sizes, int n_in,
                              void* d_out, int out_size)
{
    const float* X    = (const float*)d_in[0];
    const float* w    = (const float*)d_in[1];
    const int*   cidx = (const int*)  d_in[2];  // [N_LAYERS, N_NODES, N_CHILD]
    const int*   fids = (const int*)  d_in[3];  // [N_LAYERS, N_NODES]
    float*       out  = (float*)d_out;

    float* bufA = nullptr;
    float* bufB = nullptr;
    cudaGetSymbolAddress((void**)&bufA, g_bufA);
    cudaGetSymbolAddress((void**)&bufB, g_bufB);

    // Layer i reads ins[i], writes outs[i].
    const float* ins[N_LAYERS]  = { X, bufA, bufB, bufA, bufB, bufA, bufB, bufA };
    float*       outs[N_LAYERS] = { bufA, bufB, bufA, bufB, bufA, bufB, bufA, out };

    // 200000 nodes / 8 nodes-per-warp = 25000 warps; 8 warps/block -> 3125 blocks.
    const int threads = 256;
    const int blocks  = (N_NODES / 8 * 32 + threads - 1) / threads;  // 3125

    for (int l = 0; l < N_LAYERS; l++) {
        const int4* layer_cidx =
            (const int4*)(cidx + (size_t)l * N_NODES * N_CHILD);
        const int* layer_fids = fids + (size_t)l * N_NODES;
        layer_kernel<<<blocks, threads>>>(ins[l], outs[l], layer_cidx,
                                          layer_fids, w);
    }
}

// round 4
// speedup vs baseline: 1.0767x; 1.0010x over previous
#include <cuda_runtime.h>

#define N_NODES    200000
#define N_CHILD    32
#define N_LAYERS   8
#define N_CHUNKS   4
#define CHUNK_VALS 50000            // 50000 floats = 200KB smem; 4*50000 = 200000
#define N_RANGES   37
#define RANGE_SZ   5408             // 37*5408 >= 200000, multiple of 8
#define THREADS    1024

// Deterministic scratch (no runtime allocation allowed).
__device__ float g_vals[N_NODES];                 // post-activation layer values
__device__ float g_partial[N_CHUNKS][N_NODES];    // per-chunk partial sums

// Gather kernel. Grid = N_RANGES * N_CHUNKS blocks.
//   chunk = blockIdx.x % 4, range = blockIdx.x / 4.
// Block stages its 50K-float chunk of `src` into smem, then for every node in
// its range gathers the children whose index falls in the chunk from smem
// (predicated LDS — random-bank crossbar, ~8x cheaper than L1tex wavefronts)
// and writes the partial sum to g_partial[chunk][node].
// Warp layout (as before): 8 nodes/warp via 2 int4 index loads per lane;
// 8-lane shfl groups reduce each node.
__global__ void __launch_bounds__(THREADS, 1) gather_kernel(
    const float* __restrict__ src,     // layer-input values [N_NODES]
    const int4*  __restrict__ cidx)    // this layer's indices as int4
{
    extern __shared__ float sval[];    // CHUNK_VALS floats

    const int chunk = blockIdx.x & (N_CHUNKS - 1);
    const int range = blockIdx.x >> 2;
    const int cbase = chunk * CHUNK_VALS;

    // Stage chunk: coalesced float4 loads (src is L2-resident).
    {
        const float4* s4 = (const float4*)(src + cbase);
        float4* d4 = (float4*)sval;
        for (int i = threadIdx.x; i < CHUNK_VALS / 4; i += THREADS)
            d4[i] = s4[i];
    }
    __syncthreads();

    const int warp = threadIdx.x >> 5;
    const int lane = threadIdx.x & 31;
    const int range_start = range * RANGE_SZ;

    // Each warp-task covers 8 nodes. RANGE_SZ % 8 == 0 and N_NODES % 8 == 0,
    // so tasks never straddle the array end.
    for (int t = warp; t * 8 < RANGE_SZ; t += THREADS / 32) {
        const int node0 = range_start + t * 8;
        if (node0 >= N_NODES) break;

        const size_t ibase = (size_t)node0 * (N_CHILD / 4);
        const int4 cA = cidx[ibase + lane];
        const int4 cB = cidx[ibase + 32 + lane];

        float sA = 0.0f, sB = 0.0f;
        {
            unsigned r;
            r = (unsigned)(cA.x - cbase); if (r < CHUNK_VALS) sA += sval[r];
            r = (unsigned)(cA.y - cbase); if (r < CHUNK_VALS) sA += sval[r];
            r = (unsigned)(cA.z - cbase); if (r < CHUNK_VALS) sA += sval[r];
            r = (unsigned)(cA.w - cbase); if (r < CHUNK_VALS) sA += sval[r];
            r = (unsigned)(cB.x - cbase); if (r < CHUNK_VALS) sB += sval[r];
            r = (unsigned)(cB.y - cbase); if (r < CHUNK_VALS) sB += sval[r];
            r = (unsigned)(cB.z - cbase); if (r < CHUNK_VALS) sB += sval[r];
            r = (unsigned)(cB.w - cbase); if (r < CHUNK_VALS) sB += sval[r];
        }

        sA += __shfl_down_sync(0xffffffffu, sA, 4);
        sB += __shfl_down_sync(0xffffffffu, sB, 4);
        sA += __shfl_down_sync(0xffffffffu, sA, 2);
        sB += __shfl_down_sync(0xffffffffu, sB, 2);
        sA += __shfl_down_sync(0xffffffffu, sA, 1);
        sB += __shfl_down_sync(0xffffffffu, sB, 1);

        if ((lane & 7) == 0) {
            const int g = lane >> 3;
            g_partial[chunk][node0 + g]     = sA;
            g_partial[chunk][node0 + 4 + g] = sB;
        }
    }
}

// Combine: vals/out[n] = act( w * (p0+p1+p2+p3) ). Fully deterministic.
__global__ void __launch_bounds__(512) combine_kernel(
    float*       __restrict__ dst,
    const int*   __restrict__ fids,    // this layer's fun_ids
    const float* __restrict__ wptr)
{
    const int n = blockIdx.x * blockDim.x + threadIdx.x;
    if (n >= N_NODES) return;

    const float s = (g_partial[0][n] + g_partial[1][n])
                  + (g_partial[2][n] + g_partial[3][n]);
    const float x = wptr[0] * s;
    const int fid = __ldg(fids + n);
    float r;
    if      (fid == 0) r = tanhf(x);
    else if (fid == 1) r = 1.0f / (1.0f + expf(-x));
    else if (fid == 2) r = fmaxf(x, 0.0f);
    else               r = x;
    dst[n] = r;
}

extern "C" void kernel_launch(void* const* d_in, const int* in_sizes, int n_in,
                              void* d_out, int out_size)
{
    const float* X    = (const float*)d_in[0];
    const float* w    = (const float*)d_in[1];
    const int*   cidx = (const int*)  d_in[2];  // [N_LAYERS, N_NODES, N_CHILD]
    const int*   fids = (const int*)  d_in[3];  // [N_LAYERS, N_NODES]
    float*       out  = (float*)d_out;

    float* vals = nullptr;
    cudaGetSymbolAddress((void**)&vals, g_vals);

    // Opt in to 200KB dynamic smem (idempotent; host-side API, not captured).
    static const size_t SMEM_BYTES = (size_t)CHUNK_VALS * sizeof(float);
    cudaFuncSetAttribute(gather_kernel,
                         cudaFuncAttributeMaxDynamicSharedMemorySize,
                         (int)SMEM_BYTES);

    const int gather_grid  = N_RANGES * N_CHUNKS;      // 148
    const int combine_grid = (N_NODES + 511) / 512;    // 391

    for (int l = 0; l < N_LAYERS; l++) {
        const float* src = (l == 0) ? X : vals;
        float*       dst = (l == N_LAYERS - 1) ? out : vals;
        const int4* layer_cidx =
            (const int4*)(cidx + (size_t)l * N_NODES * N_CHILD);
        const int* layer_fids = fids + (size_t)l * N_NODES;

        gather_kernel<<<gather_grid, THREADS, SMEM_BYTES>>>(src, layer_cidx);
        combine_kernel<<<combine_grid, 512>>>(dst, layer_fids, w);
    }
}